// round 6
// baseline (speedup 1.0000x reference)
#include <cuda_runtime.h>
#include <cuda_bf16.h>
#include <math.h>

#define NN 16384
#define DD 32
#define BM 64
#define KSPLIT 2
#define KHALF (NN / KSPLIT)     // 8192
#define KCH 8
#define ND (NN * DD)            // 524288

// fp32 scratch: Part[2], T1, T2, LP, HPc
__device__ float g_Part[KSPLIT * ND];
__device__ float g_T1[ND];
__device__ float g_T2[ND];
__device__ float g_LP[ND];
__device__ float g_HP[ND];
// transposed bf16 split buffers, 2 ping-pong sets x {hi, lo}, layout [n][k] = [32][16384]
__device__ __nv_bfloat16 g_S0h[ND], g_S0l[ND], g_S1h[ND], g_S1l[ND];

// split a float2 into packed bf16x2 hi and lo (residual) u32 fragments
__device__ __forceinline__ void split2(float2 f, unsigned& hi, unsigned& lo)
{
    __nv_bfloat162 h2 = __float22bfloat162_rn(f);   // low 16 = bf16(f.x)
    hi = *(unsigned*)&h2;
    float fxh = __uint_as_float(hi << 16);
    float fyh = __uint_as_float(hi & 0xFFFF0000u);
    float2 l = make_float2(f.x - fxh, f.y - fyh);
    __nv_bfloat162 l2 = __float22bfloat162_rn(l);
    lo = *(unsigned*)&l2;
}

#define MMA(c, a0, a1, a2, a3, b0, b1)                                          \
    asm("mma.sync.aligned.m16n8k16.row.col.f32.bf16.bf16.f32 "                  \
        "{%0,%1,%2,%3},{%4,%5,%6,%7},{%8,%9},{%0,%1,%2,%3};"                    \
        : "+f"(c[0]), "+f"(c[1]), "+f"(c[2]), "+f"(c[3])                        \
        : "r"(a0), "r"(a1), "r"(a2), "r"(a3), "r"(b0), "r"(b1))

// Partial GEMM via bf16 3-term split MMA:
// Part[ks] = L[rows, kslice] @ T[kslice, :]   (T given as transposed bf16 hi/lo)
__global__ __launch_bounds__(256) void cheb_mma(
    const float* __restrict__ Lg,
    const __nv_bfloat16* __restrict__ Bhi,
    const __nv_bfloat16* __restrict__ Blo,
    float* __restrict__ Part)
{
    const int t    = threadIdx.x;
    const int lane = t & 31, w = t >> 5;
    const int wm   = w & 3, wn = w >> 2;        // 4 m-warps x 2 n-warps
    const int g    = lane >> 2, tg = lane & 3;  // groupID, thread-in-group
    const int row0 = blockIdx.x * BM;
    const int kb0  = blockIdx.y * KHALF;

    const int rA = row0 + 16 * wm + g;
    const float* pL0 = Lg + (size_t)rA * NN + kb0 + 2 * tg;     // row g
    const float* pL1 = pL0 + (size_t)8 * NN;                    // row g+8
    const int nB = 16 * wn + g;
    const __nv_bfloat16* pBh0 = Bhi + (size_t)nB * NN + kb0 + 2 * tg;
    const __nv_bfloat16* pBh1 = pBh0 + (size_t)8 * NN;          // n+8 tile
    const __nv_bfloat16* pBl0 = Blo + (size_t)nB * NN + kb0 + 2 * tg;
    const __nv_bfloat16* pBl1 = pBl0 + (size_t)8 * NN;

    float acc0[4] = {0.f, 0.f, 0.f, 0.f};
    float acc1[4] = {0.f, 0.f, 0.f, 0.f};

#pragma unroll 2
    for (int kk = 0; kk < KHALF; kk += 16) {
        // A: fp32 pairs (row g / g+8, k-cols 2tg..2tg+1 and +8)
        float2 f00 = *(const float2*)(pL0);
        float2 f01 = *(const float2*)(pL0 + 8);
        float2 f10 = *(const float2*)(pL1);
        float2 f11 = *(const float2*)(pL1 + 8);
        // B: packed bf16 k-pairs at col nB / nB+8
        unsigned bh0a = *(const unsigned*)(pBh0);
        unsigned bh0b = *(const unsigned*)(pBh0 + 8);
        unsigned bh1a = *(const unsigned*)(pBh1);
        unsigned bh1b = *(const unsigned*)(pBh1 + 8);
        unsigned bl0a = *(const unsigned*)(pBl0);
        unsigned bl0b = *(const unsigned*)(pBl0 + 8);
        unsigned bl1a = *(const unsigned*)(pBl1);
        unsigned bl1b = *(const unsigned*)(pBl1 + 8);

        unsigned ah0, al0, ah1, al1, ah2, al2, ah3, al3;
        split2(f00, ah0, al0);   // a0: row g,   k 2tg..+1
        split2(f10, ah1, al1);   // a1: row g+8, k 2tg..+1
        split2(f01, ah2, al2);   // a2: row g,   k 2tg+8..+9
        split2(f11, ah3, al3);   // a3: row g+8, k 2tg+8..+9

        // n-tile 0
        MMA(acc0, ah0, ah1, ah2, ah3, bh0a, bh0b);  // Lhi * Thi
        MMA(acc0, ah0, ah1, ah2, ah3, bl0a, bl0b);  // Lhi * Tlo
        MMA(acc0, al0, al1, al2, al3, bh0a, bh0b);  // Llo * Thi
        // n-tile 1
        MMA(acc1, ah0, ah1, ah2, ah3, bh1a, bh1b);
        MMA(acc1, ah0, ah1, ah2, ah3, bl1a, bl1b);
        MMA(acc1, al0, al1, al2, al3, bh1a, bh1b);

        pL0 += 16; pL1 += 16;
        pBh0 += 16; pBh1 += 16; pBl0 += 16; pBl1 += 16;
    }

    // store partials: C[row][col], c0/c1 at (g, 2tg..+1), c2/c3 at (g+8, ...)
    float* P = Part + (size_t)blockIdx.y * ND;
    const int col = 16 * wn + 2 * tg;
    size_t o0 = (size_t)rA * DD + col;
    *(float2*)&P[o0]              = make_float2(acc0[0], acc0[1]);
    *(float2*)&P[o0 + 8]          = make_float2(acc1[0], acc1[1]);
    *(float2*)&P[o0 + 8 * DD]     = make_float2(acc0[2], acc0[3]);
    *(float2*)&P[o0 + 8 * DD + 8] = make_float2(acc1[2], acc1[3]);
}

// Sum KSPLIT partials, apply recurrence + LP/HP accumulation, and emit the
// transposed bf16 hi/lo split of T_next for the next pass's MMA.
// first=1: tc = acc ; LP = al0*Tpv + al1*tc ; HP = ah0*Tpv + ah1*tc
// first=0: tc = 2*acc - Tpv ; LP += al1*tc ; HP += ah1*tc
__global__ __launch_bounds__(256) void cheb_recur(
    const float* __restrict__ Part, const float* __restrict__ Tpv,
    float* __restrict__ Tout,
    __nv_bfloat16* __restrict__ Shi, __nv_bfloat16* __restrict__ Slo,
    float* __restrict__ LP, float* __restrict__ HP,
    float al0, float al1, float ah0, float ah1, int first)
{
    __shared__ float sT[32][33];
    const int tx = threadIdx.x, ty = threadIdx.y;
    const int rb = blockIdx.x * 32;

#pragma unroll
    for (int i = 0; i < 4; i++) {
        int r = rb + ty + 8 * i;
        size_t idx = (size_t)r * DD + tx;
        float s  = Part[idx] + Part[(size_t)ND + idx];
        float pv = Tpv[idx];
        float tc, lp, hp;
        if (first) {
            tc = s;
            lp = al0 * pv + al1 * tc;
            hp = ah0 * pv + ah1 * tc;
        } else {
            tc = 2.f * s - pv;
            lp = LP[idx] + al1 * tc;
            hp = HP[idx] + ah1 * tc;
        }
        Tout[idx] = tc;              // may alias Tpv: same-thread RMW, safe
        LP[idx] = lp;
        HP[idx] = hp;
        sT[ty + 8 * i][tx] = tc;
    }
    __syncthreads();

#pragma unroll
    for (int i = 0; i < 4; i++) {
        int c = ty + 8 * i;
        float v = sT[tx][c];                         // element (row rb+tx, col c)
        __nv_bfloat16 h = __float2bfloat16_rn(v);
        __nv_bfloat16 l = __float2bfloat16_rn(v - __bfloat162float(h));
        size_t o = (size_t)c * NN + rb + tx;
        Shi[o] = h;
        Slo[o] = l;
    }
}

// Transpose-split X into bf16 hi/lo (B operand for pass 1)
__global__ __launch_bounds__(256) void split_x(
    const float* __restrict__ X,
    __nv_bfloat16* __restrict__ Shi, __nv_bfloat16* __restrict__ Slo)
{
    __shared__ float sT[32][33];
    const int tx = threadIdx.x, ty = threadIdx.y;
    const int rb = blockIdx.x * 32;
#pragma unroll
    for (int i = 0; i < 4; i++)
        sT[ty + 8 * i][tx] = X[(size_t)(rb + ty + 8 * i) * DD + tx];
    __syncthreads();
#pragma unroll
    for (int i = 0; i < 4; i++) {
        int c = ty + 8 * i;
        float v = sT[tx][c];
        __nv_bfloat16 h = __float2bfloat16_rn(v);
        __nv_bfloat16 l = __float2bfloat16_rn(v - __bfloat162float(h));
        size_t o = (size_t)c * NN + rb + tx;
        Shi[o] = h;
        Slo[o] = l;
    }
}

// HP = X - HPc ; H_lp = relu(LP@Wlp+blp) ; H_hp = relu(HP@Whp+bhp)
// Z = [H_lp, H_hp, X] @ Wf + bf
__global__ __launch_bounds__(256) void fuse_kernel(
    const float* __restrict__ LP, const float* __restrict__ HPc,
    const float* __restrict__ X,
    const float* __restrict__ Wlp, const float* __restrict__ blp,
    const float* __restrict__ Whp, const float* __restrict__ bhp,
    const float* __restrict__ Wf, const float* __restrict__ bf,
    float* __restrict__ Z)
{
    __shared__ float sWlp[DD * DD], sWhp[DD * DD], sWf[3 * DD * DD];
    __shared__ float sb[3][DD];
    __shared__ float sLP[8][DD], sHP[8][DD], sX[8][DD], sHl[8][DD], sHh[8][DD];

    const int j = threadIdx.x, rl = threadIdx.y;
    const int t = rl * DD + j;
    for (int i = t; i < DD * DD; i += 256) { sWlp[i] = Wlp[i]; sWhp[i] = Whp[i]; }
    for (int i = t; i < 3 * DD * DD; i += 256) sWf[i] = Wf[i];
    if (t < DD) { sb[0][t] = blp[t]; sb[1][t] = bhp[t]; sb[2][t] = bf[t]; }

    const int r = blockIdx.x * 8 + rl;
    float xv = X[r * DD + j];
    sX[rl][j]  = xv;
    sLP[rl][j] = LP[r * DD + j];
    sHP[rl][j] = xv - HPc[r * DD + j];
    __syncthreads();

    float a = sb[0][j], b = sb[1][j];
#pragma unroll
    for (int i = 0; i < DD; i++) {
        a = fmaf(sLP[rl][i], sWlp[i * DD + j], a);
        b = fmaf(sHP[rl][i], sWhp[i * DD + j], b);
    }
    sHl[rl][j] = fmaxf(a, 0.f);
    sHh[rl][j] = fmaxf(b, 0.f);
    __syncthreads();

    float z = sb[2][j];
#pragma unroll
    for (int i = 0; i < DD; i++) {
        z = fmaf(sHl[rl][i], sWf[i * DD + j], z);
        z = fmaf(sHh[rl][i], sWf[(DD + i) * DD + j], z);
        z = fmaf(sX[rl][i],  sWf[(2 * DD + i) * DD + j], z);
    }
    Z[r * DD + j] = z;
}

// a_k(tau) = (2 - d_k0) * (-1)^k * exp(-tau) * I_k(tau), 40-term series as reference
static void cheb_coeffs_host(double tau, double* a)
{
    for (int k = 0; k <= KCH; k++) {
        double s = 0.0;
        for (int m = 0; m < 40; m++) {
            double num = pow(tau * 0.5, 2 * m + k);
            double fm = 1.0, fmk = 1.0;
            for (int i = 2; i <= m; i++)     fm  *= (double)i;
            for (int i = 2; i <= m + k; i++) fmk *= (double)i;
            s += num / (fm * fmk);
        }
        a[k] = (k ? 2.0 : 1.0) * ((k & 1) ? -1.0 : 1.0) * exp(-tau) * s;
    }
}

extern "C" void kernel_launch(void* const* d_in, const int* in_sizes, int n_in,
                              void* d_out, int out_size)
{
    const float* X   = (const float*)d_in[0];
    const float* Lg  = (const float*)d_in[1];
    const float* Wlp = (const float*)d_in[2];
    const float* blp = (const float*)d_in[3];
    const float* Whp = (const float*)d_in[4];
    const float* bhp = (const float*)d_in[5];
    const float* Wf  = (const float*)d_in[6];
    const float* bf  = (const float*)d_in[7];
    float* Z = (float*)d_out;

    float *Part, *T1, *T2, *LPb, *HPb;
    __nv_bfloat16 *S0h, *S0l, *S1h, *S1l;
    { void* p; cudaGetSymbolAddress(&p, g_Part); Part = (float*)p; }
    { void* p; cudaGetSymbolAddress(&p, g_T1);   T1   = (float*)p; }
    { void* p; cudaGetSymbolAddress(&p, g_T2);   T2   = (float*)p; }
    { void* p; cudaGetSymbolAddress(&p, g_LP);   LPb  = (float*)p; }
    { void* p; cudaGetSymbolAddress(&p, g_HP);   HPb  = (float*)p; }
    { void* p; cudaGetSymbolAddress(&p, g_S0h);  S0h  = (__nv_bfloat16*)p; }
    { void* p; cudaGetSymbolAddress(&p, g_S0l);  S0l  = (__nv_bfloat16*)p; }
    { void* p; cudaGetSymbolAddress(&p, g_S1h);  S1h  = (__nv_bfloat16*)p; }
    { void* p; cudaGetSymbolAddress(&p, g_S1l);  S1l  = (__nv_bfloat16*)p; }

    double al[KCH + 1], ah[KCH + 1];
    cheb_coeffs_host(0.5, al);
    cheb_coeffs_host(1.5, ah);

    const dim3 gmma(NN / BM, KSPLIT);
    const dim3 btile(32, 8);

    // T0 = X -> split set S0
    split_x<<<NN / 32, btile>>>(X, S0h, S0l);

    // pass 1: T1 = L@X ; LP/HP init ; split -> S1
    cheb_mma<<<gmma, 256>>>(Lg, S0h, S0l, Part);
    cheb_recur<<<NN / 32, btile>>>(Part, X, T1, S1h, S1l, LPb, HPb,
        (float)al[0], (float)al[1], (float)ah[0], (float)ah[1], 1);

    // pass 2: T2 = 2*L@T1 - X ; split -> S0
    cheb_mma<<<gmma, 256>>>(Lg, S1h, S1l, Part);
    cheb_recur<<<NN / 32, btile>>>(Part, X, T2, S0h, S0l, LPb, HPb,
        0.f, (float)al[2], 0.f, (float)ah[2], 0);

    // passes 3..8: fp32 prev ping-pong T1/T2 (in-place), split sets alternate.
    // Pass k READS the set written by pass k-1 = sh[(k+1)&1], WRITES sh[k&1].
    float* prevs[2] = {T1, T2};
    __nv_bfloat16* sh[2] = {S0h, S1h};
    __nv_bfloat16* sl[2] = {S0l, S1l};
    for (int k = 3; k <= KCH; k++) {
        __nv_bfloat16* inh  = sh[(k + 1) & 1];   // split(T_{k-1}), written by pass k-1
        __nv_bfloat16* inl  = sl[(k + 1) & 1];
        __nv_bfloat16* outh = sh[k & 1];         // receives split(T_k)
        __nv_bfloat16* outl = sl[k & 1];
        float* pv = prevs[(k - 3) & 1];          // T_{k-2}, overwritten with T_k
        cheb_mma<<<gmma, 256>>>(Lg, inh, inl, Part);
        cheb_recur<<<NN / 32, btile>>>(Part, pv, pv, outh, outl, LPb, HPb,
            0.f, (float)al[k], 0.f, (float)ah[k], 0);
    }

    fuse_kernel<<<NN / 8, dim3(DD, 8)>>>(LPb, HPb, X, Wlp, blp, Whp, bhp, Wf, bf, Z);
}

// round 13
// speedup vs baseline: 3.1656x; 3.1656x over previous
#include <cuda_runtime.h>
#include <cuda_bf16.h>
#include <math.h>

#define NN 16384
#define DD 32
#define BM 64
#define BK 32
#define KSPLIT 4
#define KQ (NN / KSPLIT)     // 4096
#define NCH (KQ / BK)        // 128 chunks
#define KCH 8
#define ND (NN * DD)         // 524288
#define AP 40                // A smem pitch in bf16 (80 B) -> LDSM conflict-free
#define BP 40

__device__ float g_Part[KSPLIT * ND];
__device__ float g_T1[ND], g_T2[ND], g_LP[ND], g_HP[ND];
__device__ __nv_bfloat16 g_S0h[ND], g_S0l[ND], g_S1h[ND], g_S1l[ND];

// split a float2 into packed bf16x2 hi and lo (residual) u32
__device__ __forceinline__ void split2(float2 f, unsigned& hi, unsigned& lo)
{
    __nv_bfloat162 h2 = __float22bfloat162_rn(f);
    hi = *(unsigned*)&h2;
    float fxh = __uint_as_float(hi << 16);
    float fyh = __uint_as_float(hi & 0xFFFF0000u);
    float2 l = make_float2(f.x - fxh, f.y - fyh);
    __nv_bfloat162 l2 = __float22bfloat162_rn(l);
    lo = *(unsigned*)&l2;
}

__device__ __forceinline__ void ldsm4(unsigned& r0, unsigned& r1,
                                      unsigned& r2, unsigned& r3, unsigned addr)
{
    asm volatile("ldmatrix.sync.aligned.m8n8.x4.shared.b16 {%0,%1,%2,%3},[%4];"
                 : "=r"(r0), "=r"(r1), "=r"(r2), "=r"(r3) : "r"(addr));
}

__device__ __forceinline__ void mma16816(float* c,
    unsigned a0, unsigned a1, unsigned a2, unsigned a3,
    unsigned b0, unsigned b1)
{
    asm("mma.sync.aligned.m16n8k16.row.col.f32.bf16.bf16.f32 "
        "{%0,%1,%2,%3},{%4,%5,%6,%7},{%8,%9},{%0,%1,%2,%3};"
        : "+f"(c[0]), "+f"(c[1]), "+f"(c[2]), "+f"(c[3])
        : "r"(a0), "r"(a1), "r"(a2), "r"(a3), "r"(b0), "r"(b1));
}

// Part[ks] = L[rows, kslice] @ T[kslice, :]  (T transposed bf16 hi/lo, [n][NN])
__global__ __launch_bounds__(128, 7) void cheb_mma(
    const float* __restrict__ Lg,
    const __nv_bfloat16* __restrict__ Bhi,
    const __nv_bfloat16* __restrict__ Blo,
    float* __restrict__ Part)
{
    __shared__ __align__(16) __nv_bfloat16 Ah[BM * AP], Al[BM * AP];
    __shared__ __align__(16) __nv_bfloat16 Bh[DD * BP], Bl[DD * BP];

    const int t = threadIdx.x;
    const int lane = t & 31, w = t >> 5;
    const int wm = w & 1, wn = w >> 1;          // 2 m-warps x 2 n-warps
    const int g = lane >> 2, tg = lane & 3;
    const int row0 = blockIdx.x * BM;
    const int kb0  = blockIdx.y * KQ;

    // gmem loaders (coalesced: A warp-instr = 4 rows x 128B line each)
    const int arow = t >> 3, ac4 = t & 7;       // A: rows arow+16j, float4 col ac4
    const float* pA = Lg + (size_t)(row0 + arow) * NN + kb0 + 4 * ac4;
    const int bn = t >> 2, bq = t & 3;          // B: row bn, 16B quarter bq
    const __nv_bfloat16* pBh = Bhi + (size_t)bn * NN + kb0 + 8 * bq;
    const __nv_bfloat16* pBl = Blo + (size_t)bn * NN + kb0 + 8 * bq;

    // LDSM base addresses (byte pitch 2*AP = 80)
    const unsigned aRow = 32 * wm + (lane & 7) + (lane & 8);
    const unsigned aG   = (lane >> 4) & 1;
    unsigned ah_b = (unsigned)__cvta_generic_to_shared(Ah) + aRow * 2 * AP + aG * 16;
    unsigned al_b = (unsigned)__cvta_generic_to_shared(Al) + aRow * 2 * AP + aG * 16;
    const unsigned bRow = 16 * wn + (lane & 7) + ((lane >> 4) & 1) * 8;
    const unsigned bG   = (lane >> 3) & 1;
    unsigned bh_b = (unsigned)__cvta_generic_to_shared(Bh) + bRow * 2 * BP + bG * 16;
    unsigned bl_b = (unsigned)__cvta_generic_to_shared(Bl) + bRow * 2 * BP + bG * 16;

    float4 lreg[4];
    uint4 bh_r, bl_r;
#pragma unroll
    for (int j = 0; j < 4; j++)
        lreg[j] = *(const float4*)(pA + (size_t)16 * j * NN);
    bh_r = *(const uint4*)(pBh);
    bl_r = *(const uint4*)(pBl);

    float acc00[4] = {0.f, 0.f, 0.f, 0.f};
    float acc01[4] = {0.f, 0.f, 0.f, 0.f};
    float acc10[4] = {0.f, 0.f, 0.f, 0.f};
    float acc11[4] = {0.f, 0.f, 0.f, 0.f};

#pragma unroll 1
    for (int c = 0; c < NCH; c++) {
        // convert fp32 -> bf16 hi/lo and stage
#pragma unroll
        for (int j = 0; j < 4; j++) {
            unsigned h0, l0, h1, l1;
            split2(make_float2(lreg[j].x, lreg[j].y), h0, l0);
            split2(make_float2(lreg[j].z, lreg[j].w), h1, l1);
            int base = (arow + 16 * j) * AP + 4 * ac4;
            *(uint2*)&Ah[base] = make_uint2(h0, h1);
            *(uint2*)&Al[base] = make_uint2(l0, l1);
        }
        *(uint4*)&Bh[bn * BP + 8 * bq] = bh_r;
        *(uint4*)&Bl[bn * BP + 8 * bq] = bl_r;
        __syncthreads();

        if (c + 1 < NCH) {
#pragma unroll
            for (int j = 0; j < 4; j++)
                lreg[j] = *(const float4*)(pA + (size_t)16 * j * NN + (c + 1) * BK);
            bh_r = *(const uint4*)(pBh + (c + 1) * BK);
            bl_r = *(const uint4*)(pBl + (c + 1) * BK);
        }

#pragma unroll
        for (int ks = 0; ks < 2; ks++) {
            const unsigned ko = ks * 32;
            unsigned A0[4], A1[4], L0[4], L1[4], B0[4], C0[4];
            ldsm4(A0[0], A0[1], A0[2], A0[3], ah_b + ko);
            ldsm4(A1[0], A1[1], A1[2], A1[3], ah_b + 16 * 2 * AP + ko);
            ldsm4(B0[0], B0[1], B0[2], B0[3], bh_b + ko);
            ldsm4(C0[0], C0[1], C0[2], C0[3], bl_b + ko);
            ldsm4(L0[0], L0[1], L0[2], L0[3], al_b + ko);
            ldsm4(L1[0], L1[1], L1[2], L1[3], al_b + 16 * 2 * AP + ko);
            // hi*hi
            mma16816(acc00, A0[0], A0[1], A0[2], A0[3], B0[0], B0[1]);
            mma16816(acc01, A0[0], A0[1], A0[2], A0[3], B0[2], B0[3]);
            mma16816(acc10, A1[0], A1[1], A1[2], A1[3], B0[0], B0[1]);
            mma16816(acc11, A1[0], A1[1], A1[2], A1[3], B0[2], B0[3]);
            // hi*lo
            mma16816(acc00, A0[0], A0[1], A0[2], A0[3], C0[0], C0[1]);
            mma16816(acc01, A0[0], A0[1], A0[2], A0[3], C0[2], C0[3]);
            mma16816(acc10, A1[0], A1[1], A1[2], A1[3], C0[0], C0[1]);
            mma16816(acc11, A1[0], A1[1], A1[2], A1[3], C0[2], C0[3]);
            // lo*hi
            mma16816(acc00, L0[0], L0[1], L0[2], L0[3], B0[0], B0[1]);
            mma16816(acc01, L0[0], L0[1], L0[2], L0[3], B0[2], B0[3]);
            mma16816(acc10, L1[0], L1[1], L1[2], L1[3], B0[0], B0[1]);
            mma16816(acc11, L1[0], L1[1], L1[2], L1[3], B0[2], B0[3]);
        }
        __syncthreads();
    }

    float* P = Part + (size_t)blockIdx.y * ND;
    const float* accs[4] = {acc00, acc01, acc10, acc11};
#pragma unroll
    for (int mt = 0; mt < 2; mt++)
#pragma unroll
        for (int nt = 0; nt < 2; nt++) {
            const float* a = accs[mt * 2 + nt];
            int r = row0 + 32 * wm + 16 * mt + g;
            int col = 16 * wn + 8 * nt + 2 * tg;
            *(float2*)&P[(size_t)r * DD + col] = make_float2(a[0], a[1]);
            *(float2*)&P[(size_t)(r + 8) * DD + col] = make_float2(a[2], a[3]);
        }
}

// Sum KSPLIT partials, recurrence + LP/HP accumulation, emit transposed bf16
// hi/lo split of T_next.
__global__ __launch_bounds__(256) void cheb_recur(
    const float* __restrict__ Part, const float* __restrict__ Tpv,
    float* __restrict__ Tout,
    __nv_bfloat16* __restrict__ Shi, __nv_bfloat16* __restrict__ Slo,
    float* __restrict__ LP, float* __restrict__ HP,
    float al0, float al1, float ah0, float ah1, int first)
{
    __shared__ float sT[32][33];
    const int tx = threadIdx.x, ty = threadIdx.y;
    const int rb = blockIdx.x * 32;

#pragma unroll
    for (int i = 0; i < 4; i++) {
        int r = rb + ty + 8 * i;
        size_t idx = (size_t)r * DD + tx;
        float s = Part[idx] + Part[(size_t)ND + idx]
                + Part[2 * (size_t)ND + idx] + Part[3 * (size_t)ND + idx];
        float pv = Tpv[idx];
        float tc, lp, hp;
        if (first) {
            tc = s;
            lp = al0 * pv + al1 * tc;
            hp = ah0 * pv + ah1 * tc;
        } else {
            tc = 2.f * s - pv;
            lp = LP[idx] + al1 * tc;
            hp = HP[idx] + ah1 * tc;
        }
        Tout[idx] = tc;              // may alias Tpv: same-thread RMW, safe
        LP[idx] = lp;
        HP[idx] = hp;
        sT[ty + 8 * i][tx] = tc;
    }
    __syncthreads();

#pragma unroll
    for (int i = 0; i < 4; i++) {
        int cc = ty + 8 * i;
        float v = sT[tx][cc];
        __nv_bfloat16 h = __float2bfloat16_rn(v);
        __nv_bfloat16 l = __float2bfloat16_rn(v - __bfloat162float(h));
        size_t o = (size_t)cc * NN + rb + tx;
        Shi[o] = h;
        Slo[o] = l;
    }
}

// Transpose-split X into bf16 hi/lo
__global__ __launch_bounds__(256) void split_x(
    const float* __restrict__ X,
    __nv_bfloat16* __restrict__ Shi, __nv_bfloat16* __restrict__ Slo)
{
    __shared__ float sT[32][33];
    const int tx = threadIdx.x, ty = threadIdx.y;
    const int rb = blockIdx.x * 32;
#pragma unroll
    for (int i = 0; i < 4; i++)
        sT[ty + 8 * i][tx] = X[(size_t)(rb + ty + 8 * i) * DD + tx];
    __syncthreads();
#pragma unroll
    for (int i = 0; i < 4; i++) {
        int cc = ty + 8 * i;
        float v = sT[tx][cc];
        __nv_bfloat16 h = __float2bfloat16_rn(v);
        __nv_bfloat16 l = __float2bfloat16_rn(v - __bfloat162float(h));
        size_t o = (size_t)cc * NN + rb + tx;
        Shi[o] = h;
        Slo[o] = l;
    }
}

// HP = X - HPc ; H_lp = relu(LP@Wlp+blp) ; H_hp = relu(HP@Whp+bhp)
// Z = [H_lp, H_hp, X] @ Wf + bf
__global__ __launch_bounds__(256) void fuse_kernel(
    const float* __restrict__ LP, const float* __restrict__ HPc,
    const float* __restrict__ X,
    const float* __restrict__ Wlp, const float* __restrict__ blp,
    const float* __restrict__ Whp, const float* __restrict__ bhp,
    const float* __restrict__ Wf, const float* __restrict__ bf,
    float* __restrict__ Z)
{
    __shared__ float sWlp[DD * DD], sWhp[DD * DD], sWf[3 * DD * DD];
    __shared__ float sb[3][DD];
    __shared__ float sLP[8][DD], sHP[8][DD], sX[8][DD], sHl[8][DD], sHh[8][DD];

    const int j = threadIdx.x, rl = threadIdx.y;
    const int t = rl * DD + j;
    for (int i = t; i < DD * DD; i += 256) { sWlp[i] = Wlp[i]; sWhp[i] = Whp[i]; }
    for (int i = t; i < 3 * DD * DD; i += 256) sWf[i] = Wf[i];
    if (t < DD) { sb[0][t] = blp[t]; sb[1][t] = bhp[t]; sb[2][t] = bf[t]; }

    const int r = blockIdx.x * 8 + rl;
    float xv = X[r * DD + j];
    sX[rl][j]  = xv;
    sLP[rl][j] = LP[r * DD + j];
    sHP[rl][j] = xv - HPc[r * DD + j];
    __syncthreads();

    float a = sb[0][j], b = sb[1][j];
#pragma unroll
    for (int i = 0; i < DD; i++) {
        a = fmaf(sLP[rl][i], sWlp[i * DD + j], a);
        b = fmaf(sHP[rl][i], sWhp[i * DD + j], b);
    }
    sHl[rl][j] = fmaxf(a, 0.f);
    sHh[rl][j] = fmaxf(b, 0.f);
    __syncthreads();

    float z = sb[2][j];
#pragma unroll
    for (int i = 0; i < DD; i++) {
        z = fmaf(sHl[rl][i], sWf[i * DD + j], z);
        z = fmaf(sHh[rl][i], sWf[(DD + i) * DD + j], z);
        z = fmaf(sX[rl][i],  sWf[(2 * DD + i) * DD + j], z);
    }
    Z[r * DD + j] = z;
}

// a_k(tau) = (2 - d_k0) * (-1)^k * exp(-tau) * I_k(tau), 40-term series
static void cheb_coeffs_host(double tau, double* a)
{
    for (int k = 0; k <= KCH; k++) {
        double s = 0.0;
        for (int m = 0; m < 40; m++) {
            double num = pow(tau * 0.5, 2 * m + k);
            double fm = 1.0, fmk = 1.0;
            for (int i = 2; i <= m; i++)     fm  *= (double)i;
            for (int i = 2; i <= m + k; i++) fmk *= (double)i;
            s += num / (fm * fmk);
        }
        a[k] = (k ? 2.0 : 1.0) * ((k & 1) ? -1.0 : 1.0) * exp(-tau) * s;
    }
}

extern "C" void kernel_launch(void* const* d_in, const int* in_sizes, int n_in,
                              void* d_out, int out_size)
{
    const float* X   = (const float*)d_in[0];
    const float* Lg  = (const float*)d_in[1];
    const float* Wlp = (const float*)d_in[2];
    const float* blp = (const float*)d_in[3];
    const float* Whp = (const float*)d_in[4];
    const float* bhp = (const float*)d_in[5];
    const float* Wf  = (const float*)d_in[6];
    const float* bf  = (const float*)d_in[7];
    float* Z = (float*)d_out;

    float *Part, *T1, *T2, *LPb, *HPb;
    __nv_bfloat16 *S0h, *S0l, *S1h, *S1l;
    { void* p; cudaGetSymbolAddress(&p, g_Part); Part = (float*)p; }
    { void* p; cudaGetSymbolAddress(&p, g_T1);   T1   = (float*)p; }
    { void* p; cudaGetSymbolAddress(&p, g_T2);   T2   = (float*)p; }
    { void* p; cudaGetSymbolAddress(&p, g_LP);   LPb  = (float*)p; }
    { void* p; cudaGetSymbolAddress(&p, g_HP);   HPb  = (float*)p; }
    { void* p; cudaGetSymbolAddress(&p, g_S0h);  S0h  = (__nv_bfloat16*)p; }
    { void* p; cudaGetSymbolAddress(&p, g_S0l);  S0l  = (__nv_bfloat16*)p; }
    { void* p; cudaGetSymbolAddress(&p, g_S1h);  S1h  = (__nv_bfloat16*)p; }
    { void* p; cudaGetSymbolAddress(&p, g_S1l);  S1l  = (__nv_bfloat16*)p; }

    double al[KCH + 1], ah[KCH + 1];
    cheb_coeffs_host(0.5, al);
    cheb_coeffs_host(1.5, ah);

    const dim3 gmma(NN / BM, KSPLIT);
    const dim3 btile(32, 8);

    split_x<<<NN / 32, btile>>>(X, S0h, S0l);

    // pass 1: T1 = L@X ; LP/HP init ; split -> S1
    cheb_mma<<<gmma, 128>>>(Lg, S0h, S0l, Part);
    cheb_recur<<<NN / 32, btile>>>(Part, X, T1, S1h, S1l, LPb, HPb,
        (float)al[0], (float)al[1], (float)ah[0], (float)ah[1], 1);

    // pass 2: T2 = 2*L@T1 - X ; split -> S0
    cheb_mma<<<gmma, 128>>>(Lg, S1h, S1l, Part);
    cheb_recur<<<NN / 32, btile>>>(Part, X, T2, S0h, S0l, LPb, HPb,
        0.f, (float)al[2], 0.f, (float)ah[2], 0);

    // passes 3..8: pass k READS sh[(k+1)&1] (= split(T_{k-1})), WRITES sh[k&1]
    float* prevs[2] = {T1, T2};
    __nv_bfloat16* sh[2] = {S0h, S1h};
    __nv_bfloat16* sl[2] = {S0l, S1l};
    for (int k = 3; k <= KCH; k++) {
        __nv_bfloat16* inh  = sh[(k + 1) & 1];
        __nv_bfloat16* inl  = sl[(k + 1) & 1];
        __nv_bfloat16* outh = sh[k & 1];
        __nv_bfloat16* outl = sl[k & 1];
        float* pv = prevs[(k - 3) & 1];          // T_{k-2}, overwritten with T_k
        cheb_mma<<<gmma, 128>>>(Lg, inh, inl, Part);
        cheb_recur<<<NN / 32, btile>>>(Part, pv, pv, outh, outl, LPb, HPb,
            0.f, (float)al[k], 0.f, (float)ah[k], 0);
    }

    fuse_kernel<<<NN / 8, dim3(DD, 8)>>>(LPb, HPb, X, Wlp, blp, Whp, bhp, Wf, bf, Z);
}